// round 1
// baseline (speedup 1.0000x reference)
#include <cuda_runtime.h>
#include <math.h>

#define K_CODES   8192
#define CDIM      256
#define NQ        32768
#define OUT_ELEMS 8388608

#define BM 128
#define BN 128
#define BC 32
#define BNP 136                    // padded BN to dodge STS conflicts, /4 aligned
#define NT_TILES  (K_CODES / BN)   // 64
#define CT_CHUNKS (CDIM / BC)      // 8
#define TOTAL_Q   (NT_TILES * CT_CHUNKS)
#define SMEM_FLOATS (2*BC*BM + 2*BC*BNP)
#define SMEM_BYTES  (SMEM_FLOATS * 4)

__device__ float  g_cn[K_CODES * CDIM];   // normalized codebook
__device__ int    g_idx[NQ];
__device__ double g_acc;

// ---------------------------------------------------------------------------
__global__ void zero_acc_kernel() { g_acc = 0.0; }

// ---------------------------------------------------------------------------
// L2-normalize codebook rows: cn[k] = e[k] / max(||e[k]||, 1e-12)
__global__ void norm_codebook_kernel(const float* __restrict__ E) {
    int row  = blockIdx.x * 8 + (threadIdx.x >> 5);
    int lane = threadIdx.x & 31;
    const float4* r = (const float4*)(E + (size_t)row * CDIM);
    float4 v0 = r[lane];
    float4 v1 = r[lane + 32];
    float ss = v0.x*v0.x + v0.y*v0.y + v0.z*v0.z + v0.w*v0.w
             + v1.x*v1.x + v1.y*v1.y + v1.z*v1.z + v1.w*v1.w;
#pragma unroll
    for (int off = 16; off; off >>= 1)
        ss += __shfl_xor_sync(0xffffffffu, ss, off);
    float s = 1.0f / fmaxf(sqrtf(ss), 1e-12f);
    v0.x *= s; v0.y *= s; v0.z *= s; v0.w *= s;
    v1.x *= s; v1.y *= s; v1.z *= s; v1.w *= s;
    float4* o = (float4*)(g_cn + (size_t)row * CDIM);
    o[lane]      = v0;
    o[lane + 32] = v1;
}

// ---------------------------------------------------------------------------
// Load one (A chunk, B chunk) pair into smem.
//  A: z slice, already effectively transposed: (c, p) at Ab[c*1024 + p], coalesced.
//  B: normalized codebook rows, transposed on store into Bs[c][k].
__device__ __forceinline__ void load_chunk(float* __restrict__ As,
                                           float* __restrict__ Bs,
                                           const float* __restrict__ Ab,
                                           int q, int tid) {
    int ct = q & (CT_CHUNKS - 1);
    int nt = q >> 3;
#pragma unroll
    for (int it = 0; it < 4; it++) {
        int f  = tid + it * 256;          // 0..1023 float4 slots (32x128 floats)
        int c  = f >> 5;
        int p4 = (f & 31) << 2;
        float4 v = *(const float4*)(Ab + (size_t)(ct * BC + c) * 1024 + p4);
        *(float4*)(As + c * BM + p4) = v;
    }
    const float* Bb = g_cn + (size_t)nt * BN * CDIM + ct * BC;
#pragma unroll
    for (int it = 0; it < 4; it++) {
        int f  = tid + it * 256;          // 0..1023 float4 slots (128x32 floats)
        int k  = f >> 3;
        int c4 = (f & 7) << 2;
        float4 v = *(const float4*)(Bb + (size_t)k * CDIM + c4);
        Bs[(c4 + 0) * BNP + k] = v.x;
        Bs[(c4 + 1) * BNP + k] = v.y;
        Bs[(c4 + 2) * BNP + k] = v.z;
        Bs[(c4 + 3) * BNP + k] = v.w;
    }
}

// ---------------------------------------------------------------------------
// Fused GEMM (z @ cn^T) + streaming argmax over codes. dist never stored.
__global__ __launch_bounds__(256, 2)
void vq_argmax_kernel(const float* __restrict__ z, float* __restrict__ idx_out_f) {
    extern __shared__ float smem[];
    float* As = smem;                       // 2 buffers of BC*BM
    float* Bs = smem + 2 * BC * BM;         // 2 buffers of BC*BNP

    int tid = threadIdx.x;
    int tx  = tid & 15;
    int ty  = tid >> 4;
    int mBlk = blockIdx.x * BM;
    // n = b*1024 + hw ; z flat addr = b*262144 + c*1024 + hw
    const float* Ab = z + (size_t)(mBlk >> 10) * 262144 + (mBlk & 1023);

    float best[8];
    int   bidx[8];
#pragma unroll
    for (int i = 0; i < 8; i++) { best[i] = -INFINITY; bidx[i] = 0; }

    load_chunk(As, Bs, Ab, 0, tid);
    __syncthreads();

    int buf = 0;
    for (int nt = 0; nt < NT_TILES; nt++) {
        float acc[8][8];
#pragma unroll
        for (int i = 0; i < 8; i++)
#pragma unroll
            for (int j = 0; j < 8; j++) acc[i][j] = 0.0f;

        for (int ct = 0; ct < CT_CHUNKS; ct++) {
            int q = nt * CT_CHUNKS + ct + 1;
            if (q < TOTAL_Q)
                load_chunk(As + (buf ^ 1) * BC * BM,
                           Bs + (buf ^ 1) * BC * BNP, Ab, q, tid);

            const float* Ac = As + buf * BC * BM;
            const float* Bc = Bs + buf * BC * BNP;
#pragma unroll 8
            for (int c = 0; c < BC; c++) {
                float a[8], bb[8];
                *(float4*)&a[0]  = *(const float4*)(Ac + c * BM + ty * 8);
                *(float4*)&a[4]  = *(const float4*)(Ac + c * BM + ty * 8 + 4);
                *(float4*)&bb[0] = *(const float4*)(Bc + c * BNP + tx * 8);
                *(float4*)&bb[4] = *(const float4*)(Bc + c * BNP + tx * 8 + 4);
#pragma unroll
                for (int i = 0; i < 8; i++)
#pragma unroll
                    for (int j = 0; j < 8; j++)
                        acc[i][j] = fmaf(a[i], bb[j], acc[i][j]);
            }
            __syncthreads();
            buf ^= 1;
        }

        // per-row argmax over this 128-code tile, jnp first-max tie-break
        int k0 = nt * BN + tx * 8;
#pragma unroll
        for (int i = 0; i < 8; i++) {
            float v = acc[i][0];
            int   ix = k0;
#pragma unroll
            for (int j = 1; j < 8; j++) {
                if (acc[i][j] > v) { v = acc[i][j]; ix = k0 + j; }
            }
#pragma unroll
            for (int off = 8; off; off >>= 1) {
                float ov = __shfl_xor_sync(0xffffffffu, v, off);
                int   oi = __shfl_xor_sync(0xffffffffu, ix, off);
                if (ov > v || (ov == v && oi < ix)) { v = ov; ix = oi; }
            }
            if (v > best[i] || (v == best[i] && ix < bidx[i])) {
                best[i] = v; bidx[i] = ix;
            }
        }
    }

    if (tx == 0) {
#pragma unroll
        for (int i = 0; i < 8; i++) {
            int m = mBlk + ty * 8 + i;
            g_idx[m] = bidx[i];
            idx_out_f[m] = (float)bidx[i];
        }
    }
}

// ---------------------------------------------------------------------------
// out = zt + (z_q - zt) with exact reference rounding; accumulate sum((q-z)^2)
__global__ void gather_loss_kernel(const float* __restrict__ z,
                                   const float* __restrict__ E,
                                   float* __restrict__ out) {
    int gid = blockIdx.x * 256 + threadIdx.x;
    int b  = gid >> 18;        // / 262144
    int r  = gid & 262143;
    int c  = r >> 10;
    int hw = r & 1023;
    int n  = (b << 10) + hw;
    int k  = g_idx[n];
    float q  = E[(size_t)k * CDIM + c];
    float zv = z[gid];
    float d  = q - zv;            // matches reference (z_q - zt) rounding
    out[gid] = zv + d;            // matches reference zt + sg(z_q - zt)
    float d2 = d * d;
#pragma unroll
    for (int off = 16; off; off >>= 1)
        d2 += __shfl_xor_sync(0xffffffffu, d2, off);
    __shared__ float ws[8];
    int warp = threadIdx.x >> 5;
    int lane = threadIdx.x & 31;
    if (lane == 0) ws[warp] = d2;
    __syncthreads();
    if (warp == 0) {
        float s = (lane < 8) ? ws[lane] : 0.0f;
#pragma unroll
        for (int off = 4; off; off >>= 1)
            s += __shfl_xor_sync(0xffffffffu, s, off);
        if (lane == 0) atomicAdd(&g_acc, (double)s);
    }
}

// ---------------------------------------------------------------------------
__global__ void finalize_kernel(float* __restrict__ out) {
    double m = g_acc / (double)OUT_ELEMS;
    out[OUT_ELEMS] = (float)(0.25 * m + m);   // BETA*mean + mean
}

// ---------------------------------------------------------------------------
extern "C" void kernel_launch(void* const* d_in, const int* in_sizes, int n_in,
                              void* d_out, int out_size) {
    const float* z = (const float*)d_in[0];
    const float* E = (const float*)d_in[1];
    float* out = (float*)d_out;

    cudaFuncSetAttribute(vq_argmax_kernel,
                         cudaFuncAttributeMaxDynamicSharedMemorySize,
                         SMEM_BYTES);

    zero_acc_kernel<<<1, 1>>>();
    norm_codebook_kernel<<<K_CODES / 8, 256>>>(E);
    vq_argmax_kernel<<<NQ / BM, 256, SMEM_BYTES>>>(z, out + OUT_ELEMS + 1);
    gather_loss_kernel<<<OUT_ELEMS / 256, 256>>>(z, E, out);
    finalize_kernel<<<1, 1>>>(out);
}

// round 2
// speedup vs baseline: 1.0256x; 1.0256x over previous
#include <cuda_runtime.h>
#include <math.h>

#define K_CODES   8192
#define CDIM      256
#define NQ        32768
#define OUT_ELEMS 8388608

#define BM 128
#define BN 128
#define BC 32
#define BNP 136                    // padded BN to dodge STS conflicts, /4 aligned
#define NT_TILES  (K_CODES / BN)   // 64
#define CT_CHUNKS (CDIM / BC)      // 8
#define TOTAL_Q   (NT_TILES * CT_CHUNKS)
#define SMEM_FLOATS (2*BC*BM + 2*BC*BNP)
#define SMEM_BYTES  (SMEM_FLOATS * 4)

typedef unsigned long long ull;

__device__ float  g_cn[K_CODES * CDIM];   // normalized codebook
__device__ int    g_idx[NQ];
__device__ double g_acc;

// ---------------------------------------------------------------------------
__global__ void zero_acc_kernel() { g_acc = 0.0; }

// ---------------------------------------------------------------------------
// L2-normalize codebook rows: cn[k] = e[k] / max(||e[k]||, 1e-12)
__global__ void norm_codebook_kernel(const float* __restrict__ E) {
    int row  = blockIdx.x * 8 + (threadIdx.x >> 5);
    int lane = threadIdx.x & 31;
    const float4* r = (const float4*)(E + (size_t)row * CDIM);
    float4 v0 = r[lane];
    float4 v1 = r[lane + 32];
    float ss = v0.x*v0.x + v0.y*v0.y + v0.z*v0.z + v0.w*v0.w
             + v1.x*v1.x + v1.y*v1.y + v1.z*v1.z + v1.w*v1.w;
#pragma unroll
    for (int off = 16; off; off >>= 1)
        ss += __shfl_xor_sync(0xffffffffu, ss, off);
    float s = 1.0f / fmaxf(sqrtf(ss), 1e-12f);
    v0.x *= s; v0.y *= s; v0.z *= s; v0.w *= s;
    v1.x *= s; v1.y *= s; v1.z *= s; v1.w *= s;
    float4* o = (float4*)(g_cn + (size_t)row * CDIM);
    o[lane]      = v0;
    o[lane + 32] = v1;
}

// ---------------------------------------------------------------------------
// Load one (A chunk, B chunk) pair into smem.
__device__ __forceinline__ void load_chunk(float* __restrict__ As,
                                           float* __restrict__ Bs,
                                           const float* __restrict__ Ab,
                                           int q, int tid) {
    int ct = q & (CT_CHUNKS - 1);
    int nt = q >> 3;
#pragma unroll
    for (int it = 0; it < 4; it++) {
        int f  = tid + it * 256;          // 0..1023 float4 slots (32x128 floats)
        int c  = f >> 5;
        int p4 = (f & 31) << 2;
        float4 v = *(const float4*)(Ab + (size_t)(ct * BC + c) * 1024 + p4);
        *(float4*)(As + c * BM + p4) = v;
    }
    const float* Bb = g_cn + (size_t)nt * BN * CDIM + ct * BC;
#pragma unroll
    for (int it = 0; it < 4; it++) {
        int f  = tid + it * 256;          // 0..1023 float4 slots (128x32 floats)
        int k  = f >> 3;
        int c4 = (f & 7) << 2;
        float4 v = *(const float4*)(Bb + (size_t)k * CDIM + c4);
        Bs[(c4 + 0) * BNP + k] = v.x;
        Bs[(c4 + 1) * BNP + k] = v.y;
        Bs[(c4 + 2) * BNP + k] = v.z;
        Bs[(c4 + 3) * BNP + k] = v.w;
    }
}

// splat one f32 into both lanes of an f32x2 pair
#define SPLAT2(dst, src) \
    asm("mov.b64 %0, {%1, %1};" : "=l"(dst) : "f"(src))

#define FMA2(acc, a, b) \
    asm("fma.rn.f32x2 %0, %1, %2, %0;" : "+l"(acc) : "l"(a), "l"(b))

// ---------------------------------------------------------------------------
// Fused GEMM (z @ cn^T) + streaming argmax over codes, packed f32x2 math.
__global__ __launch_bounds__(256, 2)
void vq_argmax_kernel(const float* __restrict__ z, float* __restrict__ idx_out_f) {
    extern __shared__ float smem[];
    float* As = smem;                       // 2 buffers of BC*BM
    float* Bs = smem + 2 * BC * BM;         // 2 buffers of BC*BNP

    int tid = threadIdx.x;
    int tx  = tid & 15;
    int ty  = tid >> 4;
    int mBlk = blockIdx.x * BM;
    // n = b*1024 + hw ; z flat addr = b*262144 + c*1024 + hw
    const float* Ab = z + (size_t)(mBlk >> 10) * 262144 + (mBlk & 1023);

    float best[8];
    int   bidx[8];
#pragma unroll
    for (int i = 0; i < 8; i++) { best[i] = -INFINITY; bidx[i] = 0; }

    load_chunk(As, Bs, Ab, 0, tid);
    __syncthreads();

    int buf = 0;
    for (int nt = 0; nt < NT_TILES; nt++) {
        // row-pair packed accumulators: acc2[i2][j] = (acc[2*i2][j], acc[2*i2+1][j])
        ull acc2[4][8];
#pragma unroll
        for (int i2 = 0; i2 < 4; i2++)
#pragma unroll
            for (int j = 0; j < 8; j++) acc2[i2][j] = 0ULL;

        for (int ct = 0; ct < CT_CHUNKS; ct++) {
            int q = nt * CT_CHUNKS + ct + 1;
            if (q < TOTAL_Q)
                load_chunk(As + (buf ^ 1) * BC * BM,
                           Bs + (buf ^ 1) * BC * BNP, Ab, q, tid);

            const float* Ac = As + buf * BC * BM;
            const float* Bc = Bs + buf * BC * BNP;
#pragma unroll 8
            for (int c = 0; c < BC; c++) {
                const float* Arow = Ac + c * BM + ty * 8;
                const float* Brow = Bc + c * BNP + tx * 8;
                // a row-pairs: consecutive floats alias to aligned 64-bit pairs
                ulonglong2 av0 = *(const ulonglong2*)(Arow);
                ulonglong2 av1 = *(const ulonglong2*)(Arow + 4);
                ull a2[4];
                a2[0] = av0.x; a2[1] = av0.y; a2[2] = av1.x; a2[3] = av1.y;
                float4 b0 = *(const float4*)(Brow);
                float4 b1 = *(const float4*)(Brow + 4);
                float bsc[8] = {b0.x, b0.y, b0.z, b0.w, b1.x, b1.y, b1.z, b1.w};
#pragma unroll
                for (int j = 0; j < 8; j++) {
                    ull bj;
                    SPLAT2(bj, bsc[j]);
#pragma unroll
                    for (int i2 = 0; i2 < 4; i2++)
                        FMA2(acc2[i2][j], a2[i2], bj);
                }
            }
            __syncthreads();
            buf ^= 1;
        }

        // unpack pairs (low 32 bits = even row), then per-row argmax
        float acc[8][8];
#pragma unroll
        for (int i2 = 0; i2 < 4; i2++)
#pragma unroll
            for (int j = 0; j < 8; j++) {
                acc[2 * i2 + 0][j] = __uint_as_float((unsigned)(acc2[i2][j] & 0xffffffffULL));
                acc[2 * i2 + 1][j] = __uint_as_float((unsigned)(acc2[i2][j] >> 32));
            }

        int k0 = nt * BN + tx * 8;
#pragma unroll
        for (int i = 0; i < 8; i++) {
            float v = acc[i][0];
            int   ix = k0;
#pragma unroll
            for (int j = 1; j < 8; j++) {
                if (acc[i][j] > v) { v = acc[i][j]; ix = k0 + j; }
            }
#pragma unroll
            for (int off = 8; off; off >>= 1) {
                float ov = __shfl_xor_sync(0xffffffffu, v, off);
                int   oi = __shfl_xor_sync(0xffffffffu, ix, off);
                if (ov > v || (ov == v && oi < ix)) { v = ov; ix = oi; }
            }
            if (v > best[i] || (v == best[i] && ix < bidx[i])) {
                best[i] = v; bidx[i] = ix;
            }
        }
    }

    if (tx == 0) {
#pragma unroll
        for (int i = 0; i < 8; i++) {
            int m = mBlk + ty * 8 + i;
            g_idx[m] = bidx[i];
            idx_out_f[m] = (float)bidx[i];
        }
    }
}

// ---------------------------------------------------------------------------
// out = zt + (z_q - zt) with exact reference rounding; accumulate sum((q-z)^2)
__global__ void gather_loss_kernel(const float* __restrict__ z,
                                   const float* __restrict__ E,
                                   float* __restrict__ out) {
    int gid = blockIdx.x * 256 + threadIdx.x;
    int b  = gid >> 18;        // / 262144
    int r  = gid & 262143;
    int c  = r >> 10;
    int hw = r & 1023;
    int n  = (b << 10) + hw;
    int k  = g_idx[n];
    float q  = E[(size_t)k * CDIM + c];
    float zv = z[gid];
    float d  = q - zv;            // matches reference (z_q - zt) rounding
    out[gid] = zv + d;            // matches reference zt + sg(z_q - zt)
    float d2 = d * d;
#pragma unroll
    for (int off = 16; off; off >>= 1)
        d2 += __shfl_xor_sync(0xffffffffu, d2, off);
    __shared__ float ws[8];
    int warp = threadIdx.x >> 5;
    int lane = threadIdx.x & 31;
    if (lane == 0) ws[warp] = d2;
    __syncthreads();
    if (warp == 0) {
        float s = (lane < 8) ? ws[lane] : 0.0f;
#pragma unroll
        for (int off = 4; off; off >>= 1)
            s += __shfl_xor_sync(0xffffffffu, s, off);
        if (lane == 0) atomicAdd(&g_acc, (double)s);
    }
}

// ---------------------------------------------------------------------------
__global__ void finalize_kernel(float* __restrict__ out) {
    double m = g_acc / (double)OUT_ELEMS;
    out[OUT_ELEMS] = (float)(0.25 * m + m);   // BETA*mean + mean
}

// ---------------------------------------------------------------------------
extern "C" void kernel_launch(void* const* d_in, const int* in_sizes, int n_in,
                              void* d_out, int out_size) {
    const float* z = (const float*)d_in[0];
    const float* E = (const float*)d_in[1];
    float* out = (float*)d_out;

    cudaFuncSetAttribute(vq_argmax_kernel,
                         cudaFuncAttributeMaxDynamicSharedMemorySize,
                         SMEM_BYTES);

    zero_acc_kernel<<<1, 1>>>();
    norm_codebook_kernel<<<K_CODES / 8, 256>>>(E);
    vq_argmax_kernel<<<NQ / BM, 256, SMEM_BYTES>>>(z, out + OUT_ELEMS + 1);
    gather_loss_kernel<<<OUT_ELEMS / 256, 256>>>(z, E, out);
    finalize_kernel<<<1, 1>>>(out);
}

// round 4
// speedup vs baseline: 1.2970x; 1.2647x over previous
#include <cuda_runtime.h>
#include <math.h>
#include <stdint.h>

#define K_CODES   8192
#define CDIM      256
#define NQ        32768
#define OUT_ELEMS 8388608

#define MT 128                 // M per CTA
#define NT 256                 // N per CTA tile
#define KC 32                  // K per chunk
#define PAD 36                 // smem row stride (floats), conflict-free frags
#define N_TILES (K_CODES/NT)   // 32
#define K_CHUNKS (CDIM/KC)     // 8

// smem float offsets
#define AHI_F 0
#define ALO_F 4608             // 128*36
#define BHI_F 9216
#define BLO_F 18432            // 9216 + 256*36
#define STAGE_F 27648
#define SMEM_BYTES (2 * STAGE_F * 4)   // 221184

__device__ float  g_ahi[(size_t)NQ * CDIM];
__device__ float  g_alo[(size_t)NQ * CDIM];
__device__ float  g_bhi[(size_t)K_CODES * CDIM];
__device__ float  g_blo[(size_t)K_CODES * CDIM];
__device__ float  g_cn [(size_t)K_CODES * CDIM];
__device__ float2 g_topv[NQ];
__device__ int2   g_topi[NQ];
__device__ int    g_idx[NQ];
__device__ double g_acc;

// ---------------------------------------------------------------------------
__device__ __forceinline__ void cp16(uint32_t dst, const void* src) {
    asm volatile("cp.async.cg.shared.global [%0], [%1], 16;" :: "r"(dst), "l"(src));
}
#define CP_COMMIT() asm volatile("cp.async.commit_group;" ::: "memory")
#define CP_WAIT0()  asm volatile("cp.async.wait_group 0;" ::: "memory")

__device__ __forceinline__ uint32_t smem_u32(const void* p) {
    uint32_t a;
    asm("{ .reg .u64 t; cvta.to.shared.u64 t, %1; cvt.u32.u64 %0, t; }"
        : "=r"(a) : "l"(p));
    return a;
}

#define MMA_TF32(d, a, b) \
    asm volatile("mma.sync.aligned.m16n8k8.row.col.f32.tf32.tf32.f32 " \
        "{%0,%1,%2,%3}, {%4,%5,%6,%7}, {%8,%9}, {%0,%1,%2,%3};" \
        : "+f"((d)[0]), "+f"((d)[1]), "+f"((d)[2]), "+f"((d)[3]) \
        : "r"((a)[0]), "r"((a)[1]), "r"((a)[2]), "r"((a)[3]), \
          "r"((b)[0]), "r"((b)[1]))

__device__ __forceinline__ void tf32_split(float x, float& hi, float& lo) {
    uint32_t h;
    asm("cvt.rna.tf32.f32 %0, %1;" : "=r"(h) : "f"(x));
    hi = __uint_as_float(h);
    float r = x - hi;
    uint32_t l;
    asm("cvt.rna.tf32.f32 %0, %1;" : "=r"(l) : "f"(r));
    lo = __uint_as_float(l);
}

// "better" with first-index tie-break (matches jnp.argmax)
__device__ __forceinline__ bool better(float v, int i, float V, int I) {
    return (v > V) || (v == V && i < I);
}
__device__ __forceinline__ void top2_ins(float v, int i,
                                         float& v1, int& i1, float& v2, int& i2) {
    if (better(v, i, v1, i1)) { v2 = v1; i2 = i1; v1 = v; i1 = i; }
    else if (better(v, i, v2, i2)) { v2 = v; i2 = i; }
}

// ---------------------------------------------------------------------------
__global__ void zero_acc_kernel() { g_acc = 0.0; }

// Transpose z [B,C,H,W] -> A [n=b*1024+hw][C], tf32 hi/lo split.
__global__ void split_z_kernel(const float* __restrict__ z) {
    __shared__ float th[32][33], tl[32][33];
    int tid = threadIdx.x;
    int hw0 = blockIdx.x * 32, c0 = blockIdx.y * 32, b = blockIdx.z;
#pragma unroll
    for (int i = 0; i < 4; i++) {
        int e = tid + i * 256;
        int cc = e >> 5, hh = e & 31;
        float x = z[(size_t)b * 262144 + (size_t)(c0 + cc) * 1024 + hw0 + hh];
        float h, l;
        tf32_split(x, h, l);
        th[cc][hh] = h;
        tl[cc][hh] = l;
    }
    __syncthreads();
#pragma unroll
    for (int i = 0; i < 4; i++) {
        int e = tid + i * 256;
        int hh = e >> 5, cc = e & 31;
        size_t o = (size_t)(b * 1024 + hw0 + hh) * CDIM + c0 + cc;
        g_ahi[o] = th[cc][hh];
        g_alo[o] = tl[cc][hh];
    }
}

// Normalize codebook rows, store exact cn + tf32 hi/lo.
__global__ void norm_split_codebook(const float* __restrict__ E) {
    int row  = blockIdx.x * 8 + (threadIdx.x >> 5);
    int lane = threadIdx.x & 31;
    const float4* r4 = (const float4*)(E + (size_t)row * CDIM);
    float4 v0 = r4[lane];
    float4 v1 = r4[lane + 32];
    float ss = v0.x*v0.x + v0.y*v0.y + v0.z*v0.z + v0.w*v0.w
             + v1.x*v1.x + v1.y*v1.y + v1.z*v1.z + v1.w*v1.w;
#pragma unroll
    for (int off = 16; off; off >>= 1)
        ss += __shfl_xor_sync(0xffffffffu, ss, off);
    float s = 1.0f / fmaxf(sqrtf(ss), 1e-12f);
    float xs[8] = {v0.x*s, v0.y*s, v0.z*s, v0.w*s, v1.x*s, v1.y*s, v1.z*s, v1.w*s};
    float hs[8], ls[8];
#pragma unroll
    for (int j = 0; j < 8; j++) tf32_split(xs[j], hs[j], ls[j]);
    float4* oc = (float4*)(g_cn  + (size_t)row * CDIM);
    float4* oh = (float4*)(g_bhi + (size_t)row * CDIM);
    float4* ol = (float4*)(g_blo + (size_t)row * CDIM);
    oc[lane]      = make_float4(xs[0], xs[1], xs[2], xs[3]);
    oc[lane + 32] = make_float4(xs[4], xs[5], xs[6], xs[7]);
    oh[lane]      = make_float4(hs[0], hs[1], hs[2], hs[3]);
    oh[lane + 32] = make_float4(hs[4], hs[5], hs[6], hs[7]);
    ol[lane]      = make_float4(ls[0], ls[1], ls[2], ls[3]);
    ol[lane + 32] = make_float4(ls[4], ls[5], ls[6], ls[7]);
}

// ---------------------------------------------------------------------------
__device__ __forceinline__ void load_chunk(uint32_t sb_addr, int tid,
                                           int mBlk, int nt, int ct) {
    int co = ct * KC;
    const float* Ah = g_ahi + (size_t)mBlk * CDIM + co;
    const float* Al = g_alo + (size_t)mBlk * CDIM + co;
    const float* Bh = g_bhi + (size_t)nt * NT * CDIM + co;
    const float* Bl = g_blo + (size_t)nt * NT * CDIM + co;
#pragma unroll
    for (int i = 0; i < 4; i++) {
        int f = tid + i * 256;
        int r = f >> 3, c4 = (f & 7) << 2;
        uint32_t so = (uint32_t)(r * PAD + c4) * 4;
        cp16(sb_addr + AHI_F * 4 + so, Ah + (size_t)r * CDIM + c4);
        cp16(sb_addr + ALO_F * 4 + so, Al + (size_t)r * CDIM + c4);
    }
#pragma unroll
    for (int i = 0; i < 8; i++) {
        int f = tid + i * 256;
        int r = f >> 3, c4 = (f & 7) << 2;
        uint32_t so = (uint32_t)(r * PAD + c4) * 4;
        cp16(sb_addr + BHI_F * 4 + so, Bh + (size_t)r * CDIM + c4);
        cp16(sb_addr + BLO_F * 4 + so, Bl + (size_t)r * CDIM + c4);
    }
}

// ---------------------------------------------------------------------------
// HMMA tf32 3-pass GEMM + streaming per-row top-2 argmax.
__global__ __launch_bounds__(256, 1)
void vq_mma_kernel() {
    extern __shared__ float smem[];
    uint32_t smem_b = smem_u32(smem);
    int tid = threadIdx.x;
    int wid = tid >> 5, lane = tid & 31;
    int gid = lane >> 2, tig = lane & 3;
    int wm = wid >> 2, wn = wid & 3;
    int mBlk = blockIdx.x * MT;

    // scratch (in stage0 region, only used in epilogue)
    float2* scr_v = (float2*)smem;                // 128*4 float2 = 4KB
    int2*   scr_i = (int2*)(smem + 1024);         // next 4KB

    float r1v = -INFINITY, r2v = -INFINITY;
    int   r1i = 0x7fffffff, r2i = 0x7fffffff;

    load_chunk(smem_b, tid, mBlk, 0, 0);
    CP_COMMIT();

#pragma unroll 1
    for (int nt = 0; nt < N_TILES; nt++) {
        float acc[4][8][4];
#pragma unroll
        for (int mf = 0; mf < 4; mf++)
#pragma unroll
            for (int nf = 0; nf < 8; nf++)
#pragma unroll
                for (int q = 0; q < 4; q++) acc[mf][nf][q] = 0.0f;

#pragma unroll 1
        for (int ct = 0; ct < K_CHUNKS; ct++) {
            int it = nt * K_CHUNKS + ct;
            int sb = it & 1;
            CP_WAIT0();
            __syncthreads();
            if (ct != K_CHUNKS - 1) {
                load_chunk(smem_b + (sb ^ 1) * STAGE_F * 4, tid, mBlk, nt, ct + 1);
                CP_COMMIT();
            }
            const float* S = smem + sb * STAGE_F;
            const float* SaH = S + AHI_F;
            const float* SaL = S + ALO_F;
            const float* SbH = S + BHI_F;
            const float* SbL = S + BLO_F;
#pragma unroll
            for (int k8 = 0; k8 < 4; k8++) {
                int kb = k8 * 8;
                uint32_t ah[4][4], al[4][4], bh[8][2], bl[8][2];
#pragma unroll
                for (int mf = 0; mf < 4; mf++) {
                    const float* p = SaH + (wm*64 + mf*16 + gid) * PAD + kb + tig;
                    ah[mf][0] = __float_as_uint(p[0]);
                    ah[mf][1] = __float_as_uint(p[8 * PAD]);
                    ah[mf][2] = __float_as_uint(p[4]);
                    ah[mf][3] = __float_as_uint(p[8 * PAD + 4]);
                }
#pragma unroll
                for (int nf = 0; nf < 8; nf++) {
                    const float* p = SbH + (wn*64 + nf*8 + gid) * PAD + kb + tig;
                    bh[nf][0] = __float_as_uint(p[0]);
                    bh[nf][1] = __float_as_uint(p[4]);
                }
#pragma unroll
                for (int mf = 0; mf < 4; mf++)
#pragma unroll
                    for (int nf = 0; nf < 8; nf++)
                        MMA_TF32(acc[mf][nf], ah[mf], bh[nf]);
#pragma unroll
                for (int nf = 0; nf < 8; nf++) {
                    const float* p = SbL + (wn*64 + nf*8 + gid) * PAD + kb + tig;
                    bl[nf][0] = __float_as_uint(p[0]);
                    bl[nf][1] = __float_as_uint(p[4]);
                }
#pragma unroll
                for (int mf = 0; mf < 4; mf++)
#pragma unroll
                    for (int nf = 0; nf < 8; nf++)
                        MMA_TF32(acc[mf][nf], ah[mf], bl[nf]);
#pragma unroll
                for (int mf = 0; mf < 4; mf++) {
                    const float* p = SaL + (wm*64 + mf*16 + gid) * PAD + kb + tig;
                    al[mf][0] = __float_as_uint(p[0]);
                    al[mf][1] = __float_as_uint(p[8 * PAD]);
                    al[mf][2] = __float_as_uint(p[4]);
                    al[mf][3] = __float_as_uint(p[8 * PAD + 4]);
                }
#pragma unroll
                for (int mf = 0; mf < 4; mf++)
#pragma unroll
                    for (int nf = 0; nf < 8; nf++)
                        MMA_TF32(acc[mf][nf], al[mf], bh[nf]);
            }
        }

        // ---- per-ntile top-2 epilogue (scratch lives in stage0) ----
        int ntbase = nt * NT;
#pragma unroll
        for (int mf = 0; mf < 4; mf++) {
#pragma unroll
            for (int half = 0; half < 2; half++) {
                float v1 = -INFINITY, v2 = -INFINITY;
                int   i1 = 0x7fffffff, i2 = 0x7fffffff;
#pragma unroll
                for (int nf = 0; nf < 8; nf++) {
#pragma unroll
                    for (int p = 0; p < 2; p++) {
                        float v = acc[mf][nf][half * 2 + p];
                        int col = ntbase + wn * 64 + nf * 8 + 2 * tig + p;
                        top2_ins(v, col, v1, i1, v2, i2);
                    }
                }
#pragma unroll
                for (int off = 1; off <= 2; off <<= 1) {
                    float ov1 = __shfl_xor_sync(0xffffffffu, v1, off);
                    float ov2 = __shfl_xor_sync(0xffffffffu, v2, off);
                    int   oi1 = __shfl_xor_sync(0xffffffffu, i1, off);
                    int   oi2 = __shfl_xor_sync(0xffffffffu, i2, off);
                    top2_ins(ov1, oi1, v1, i1, v2, i2);
                    top2_ins(ov2, oi2, v1, i1, v2, i2);
                }
                if (tig == 0) {
                    int rl = wm * 64 + mf * 16 + half * 8 + gid;
                    scr_v[rl * 4 + wn] = make_float2(v1, v2);
                    scr_i[rl * 4 + wn] = make_int2(i1, i2);
                }
            }
        }
        __syncthreads();
        if (tid < 128) {
#pragma unroll
            for (int w = 0; w < 4; w++) {
                float2 vv = scr_v[tid * 4 + w];
                int2   ii = scr_i[tid * 4 + w];
                top2_ins(vv.x, ii.x, r1v, r1i, r2v, r2i);
                top2_ins(vv.y, ii.y, r1v, r1i, r2v, r2i);
            }
        }
        __syncthreads();
        if (nt != N_TILES - 1) {
            load_chunk(smem_b, tid, mBlk, nt + 1, 0);   // stage0: next it is even
            CP_COMMIT();
        }
    }

    if (tid < 128) {
        g_topv[mBlk + tid] = make_float2(r1v, r2v);
        g_topi[mBlk + tid] = make_int2(r1i, r2i);
    }
}

// ---------------------------------------------------------------------------
// Rescore ambiguous rows (top-2 gap < eps) in exact fp32; write indices.
__global__ void fixup_kernel(const float* __restrict__ z,
                             float* __restrict__ idx_out_f) {
    int n = blockIdx.x * 256 + threadIdx.x;
    float2 tv = g_topv[n];
    int2   ti = g_topi[n];
    int ix = ti.x;
    if (tv.x - tv.y < 1e-3f) {
        int b = n >> 10, hw = n & 1023;
        const float* zr = z + (size_t)b * 262144 + hw;
        const float* c1 = g_cn + (size_t)ti.x * CDIM;
        const float* c2 = g_cn + (size_t)ti.y * CDIM;
        float d1 = 0.0f, d2 = 0.0f;
        for (int c = 0; c < CDIM; c++) {
            float zv = zr[(size_t)c * 1024];
            d1 = fmaf(zv, c1[c], d1);
            d2 = fmaf(zv, c2[c], d2);
        }
        if (better(d2, ti.y, d1, ti.x)) ix = ti.y;
    }
    g_idx[n] = ix;
    idx_out_f[n] = (float)ix;
}

// ---------------------------------------------------------------------------
__global__ void gather_loss_kernel(const float* __restrict__ z,
                                   const float* __restrict__ E,
                                   float* __restrict__ out) {
    int gid = blockIdx.x * 256 + threadIdx.x;
    int b  = gid >> 18;
    int r  = gid & 262143;
    int c  = r >> 10;
    int hw = r & 1023;
    int n  = (b << 10) + hw;
    int k  = g_idx[n];
    float q  = E[(size_t)k * CDIM + c];
    float zv = z[gid];
    float d  = q - zv;
    out[gid] = zv + d;
    float d2 = d * d;
#pragma unroll
    for (int off = 16; off; off >>= 1)
        d2 += __shfl_xor_sync(0xffffffffu, d2, off);
    __shared__ float ws[8];
    int warp = threadIdx.x >> 5;
    int lane = threadIdx.x & 31;
    if (lane == 0) ws[warp] = d2;
    __syncthreads();
    if (warp == 0) {
        float s = (lane < 8) ? ws[lane] : 0.0f;
#pragma unroll
        for (int off = 4; off; off >>= 1)
            s += __shfl_xor_sync(0xffffffffu, s, off);
        if (lane == 0) atomicAdd(&g_acc, (double)s);
    }
}

// ---------------------------------------------------------------------------
__global__ void finalize_kernel(float* __restrict__ out) {
    double m = g_acc / (double)OUT_ELEMS;
    out[OUT_ELEMS] = (float)(0.25 * m + m);
}

// ---------------------------------------------------------------------------
extern "C" void kernel_launch(void* const* d_in, const int* in_sizes, int n_in,
                              void* d_out, int out_size) {
    const float* z = (const float*)d_in[0];
    const float* E = (const float*)d_in[1];
    float* out = (float*)d_out;

    cudaFuncSetAttribute(vq_mma_kernel,
                         cudaFuncAttributeMaxDynamicSharedMemorySize, SMEM_BYTES);

    zero_acc_kernel<<<1, 1>>>();
    split_z_kernel<<<dim3(32, 8, 32), 256>>>(z);
    norm_split_codebook<<<K_CODES / 8, 256>>>(E);
    vq_mma_kernel<<<NQ / MT, 256, SMEM_BYTES>>>();
    fixup_kernel<<<NQ / 256, 256>>>(z, out + OUT_ELEMS + 1);
    gather_loss_kernel<<<OUT_ELEMS / 256, 256>>>(z, E, out);
    finalize_kernel<<<1, 1>>>(out);
}